// round 14
// baseline (speedup 1.0000x reference)
#include <cuda_runtime.h>
#include <cuda_bf16.h>
#include <cstdint>

// LocallyConnected2d: out[b,o,y,x] = sum_{c,k} x[b,c,y+i,x+j] * w[o,c,y,x,k]
// B=16, C_IN=16, C_OUT=16, H=W=64, OH=OW=62, K=3x3.
//
// R14 = R9 compute core + "last block reduces" epilogue: all 4 c-split
// blocks of a tile STG partials into tile-major scratch, atomicInc a per-
// tile counter (wrapping -> self-resetting across graph replays); the 4th
// arriver sums the 4 partials in fixed order (deterministic) and writes out.
// Reduction overlaps compute; no second kernel, no memset, no spin-wait.

#define B_  16
#define CIN 16
#define CO  16
#define H_  64
#define W_  64
#define OH_ 62
#define OW_ 62
#define TX  16
#define NT  128

#define NC  4                       // channels per block (4-way c split)
#define WROW 148                    // weight smem row stride (floats, 16B mult)
#define WBUF (CO * WROW)            // 2368 floats
#define XBUF (4 * 3 * 80)           // 960 floats: [bquad][row][col*4 + bl]
#define BQS  240                    // bquad stride (floats)

#define WOSTRIDE (CIN * OH_ * OW_ * 9)   // weight float stride per o
#define WCSTRIDE (OH_ * OW_ * 9)         // weight float stride per c
#define XCSTRIDE (H_ * W_)               // x float stride per c

#define NTILE (4 * OH_)             // 248 tiles
#define TSZ   4096                  // floats per tile partial (16b*16o*16x)

__device__ __align__(16) float g_scratch[4 * NTILE * TSZ];
__device__ unsigned int g_cnt[NTILE];   // zero-init; wraps back to 0 each run

__device__ __forceinline__ void ffma2(unsigned long long& d,
                                      unsigned long long a,
                                      unsigned long long b) {
    asm("fma.rn.f32x2 %0, %1, %2, %0;" : "+l"(d) : "l"(a), "l"(b));
}

__device__ __forceinline__ unsigned long long bcast2(float v) {
    unsigned long long p;
    asm("mov.b64 %0, {%1, %1};" : "=l"(p) : "f"(v));
    return p;
}

__device__ __forceinline__ void cp_async16(uint32_t dst, const float* src) {
    asm volatile("cp.async.cg.shared.global [%0], [%1], 16;\n"
                 :: "r"(dst), "l"(src));
}

__device__ __forceinline__ void cp_async4(uint32_t dst, const float* src, int sz) {
    asm volatile("cp.async.ca.shared.global [%0], [%1], 4, %2;\n"
                 :: "r"(dst), "l"(src), "r"(sz));
}

__device__ __forceinline__ void stg_v2(float* p, float a, float b) {
    asm volatile("st.global.v2.f32 [%0], {%1, %2};"
                 :: "l"(p), "f"(a), "f"(b) : "memory");
}

__global__ __launch_bounds__(NT, 5)
void lc2d_kernel(const float* __restrict__ xin,
                 const float* __restrict__ wgt,
                 float* __restrict__ out) {
    __shared__ __align__(16) float sh_w[3 * WBUF];
    __shared__ __align__(16) float sh_x[3 * XBUF];
    __shared__ int sh_last;

    const int tid = threadIdx.x;
    const int xl  = tid & 15;
    const int grp = tid >> 4;      // 0..7
    const int bh  = grp & 1;       // b half
    const int ob  = grp >> 1;      // o group

    const int y    = blockIdx.y;
    const int x0   = blockIdx.x * TX;
    const int xt   = min(TX, OW_ - x0);     // 16 or 14
    const int zz   = blockIdx.z;
    const int c0   = zz * NC;
    const int tile = blockIdx.y * 4 + blockIdx.x;
    const int sh   = 2 * (y & 1);           // uniform 16B-alignment shift

    const uint32_t shw_base = (uint32_t)__cvta_generic_to_shared(sh_w);
    const uint32_t shx_base = (uint32_t)__cvta_generic_to_shared(sh_x);

    // ---- weight staging descriptors (16B chunks, 5 slots) ----
    const int rowch  = (xt == TX) ? 37 : 32;
    const int nchunk = CO * rowch;
    const float* wcbase = wgt + (((c0 * OH_ + y) * OW_ + x0) * 9) - sh;

    int      wsoff[5];
    uint32_t wdst[5];
    bool     wok[5];
    #pragma unroll
    for (int n = 0; n < 5; ++n) {
        int m = tid + NT * n;
        wok[n] = (m < nchunk);
        int o   = m / rowch;
        int ci4 = (m - o * rowch) * 4;
        if (o > 15) { o = 15; ci4 = 0; }
        wsoff[n] = o * WOSTRIDE + ci4;
        wdst[n]  = (uint32_t)(o * WROW + ci4) * 4;
    }

    // ---- x staging descriptors (4B, b-quad interleaved, 7 slots) ----
    int      xsrcoff[7], xsz[7];
    uint32_t xdst[7];
    bool     xvalid[7];
    #pragma unroll
    for (int n = 0; n < 7; ++n) {
        int m = tid + NT * n;
        xvalid[n] = (m < B_ * 54);
        int b   = m / 54;
        int rem = m - b * 54;
        int r   = rem / 18;
        int cc  = rem - r * 18;
        if (!xvalid[n]) { b = 0; r = 0; cc = 0; }
        bool ok = xvalid[n] && (x0 + cc < W_);
        xsrcoff[n] = (b * CIN) * XCSTRIDE + r * W_ + cc;
        xsz[n]     = ok ? 4 : 0;
        xdst[n] = (uint32_t)((b >> 2) * BQS + r * 80 + cc * 4 + (b & 3)) * 4;
    }
    const float* xbase = xin + (c0 * H_ + y) * W_ + x0;

    unsigned long long acc[4][2][2];    // [oo][q][pair]: b=(bh*2+q)*4+2*pair
    #pragma unroll
    for (int oo = 0; oo < 4; ++oo)
        #pragma unroll
        for (int q = 0; q < 2; ++q) { acc[oo][q][0] = 0ull; acc[oo][q][1] = 0ull; }

    auto stage = [&](int buf, int ci) {
        uint32_t wb = shw_base + (uint32_t)buf * (WBUF * 4);
        const float* wc = wcbase + ci * WCSTRIDE;
        #pragma unroll
        for (int n = 0; n < 5; ++n)
            if (wok[n]) cp_async16(wb + wdst[n], wc + wsoff[n]);
        uint32_t xb = shx_base + (uint32_t)buf * (XBUF * 4);
        const float* xc = xbase + ci * XCSTRIDE;
        #pragma unroll
        for (int n = 0; n < 7; ++n)
            if (xvalid[n])
                cp_async4(xb + xdst[n], xc + xsrcoff[n], xsz[n]);
        asm volatile("cp.async.commit_group;\n" ::: "memory");
    };

    stage(0, 0);
    stage(1, 1);

    int rd = 0;
    #pragma unroll 1
    for (int ci = 0; ci < NC; ++ci) {
        if (ci < NC - 1) {
            asm volatile("cp.async.wait_group 1;\n" ::: "memory");
        } else {
            asm volatile("cp.async.wait_group 0;\n" ::: "memory");
        }
        __syncthreads();

        if (ci + 2 < NC) {
            int st = rd - 1; if (st < 0) st += 3;
            stage(st, ci + 2);
        }

        const float* swb = sh_w + rd * WBUF + sh;
        const float* sxb = sh_x + rd * XBUF + bh * (2 * BQS);

        #pragma unroll
        for (int k = 0; k < 9; ++k) {
            const int i = k / 3;
            const int j = k - i * 3;
            const float* xp = &sxb[i * 80 + (xl + j) * 4];
            ulonglong2 xq0 = *reinterpret_cast<const ulonglong2*>(xp);
            ulonglong2 xq1 = *reinterpret_cast<const ulonglong2*>(xp + BQS);
            #pragma unroll
            for (int oo = 0; oo < 4; ++oo) {
                float wv = swb[(ob * 4 + oo) * WROW + xl * 9 + k];
                unsigned long long wb2 = bcast2(wv);
                ffma2(acc[oo][0][0], xq0.x, wb2);
                ffma2(acc[oo][0][1], xq0.y, wb2);
                ffma2(acc[oo][1][0], xq1.x, wb2);
                ffma2(acc[oo][1][1], xq1.y, wb2);
            }
        }

        ++rd; if (rd == 3) rd = 0;
    }

    // ---- write partial into tile-major scratch (coalesced, aligned) ----
    {
        float* dst = g_scratch + ((size_t)zz * NTILE + tile) * TSZ;
        #pragma unroll
        for (int oo = 0; oo < 4; ++oo) {
            const int o = ob * 4 + oo;
            #pragma unroll
            for (int q = 0; q < 2; ++q) {
                const int bq = (bh * 2 + q) * 4;
                #pragma unroll
                for (int p = 0; p < 2; ++p) {
                    float lo, hi;
                    asm("mov.b64 {%0, %1}, %2;"
                        : "=f"(lo), "=f"(hi) : "l"(acc[oo][q][p]));
                    const int b = bq + 2 * p;
                    dst[((b * CO + o)     << 4) + xl] = lo;
                    dst[(((b + 1) * CO + o) << 4) + xl] = hi;
                }
            }
        }
    }

    // ---- last block of this tile reduces (CUDA threadFence pattern) ----
    __threadfence();
    __syncthreads();                 // all threads' stores fenced
    if (tid == 0)
        sh_last = (atomicInc(&g_cnt[tile], 3) == 3);
    __syncthreads();

    if (sh_last) {
        __threadfence();             // acquire side
        const float4* s0 = reinterpret_cast<const float4*>(
            g_scratch + ((size_t)0 * NTILE + tile) * TSZ);
        const float4* s1 = reinterpret_cast<const float4*>(
            g_scratch + ((size_t)1 * NTILE + tile) * TSZ);
        const float4* s2 = reinterpret_cast<const float4*>(
            g_scratch + ((size_t)2 * NTILE + tile) * TSZ);
        const float4* s3 = reinterpret_cast<const float4*>(
            g_scratch + ((size_t)3 * NTILE + tile) * TSZ);

        #pragma unroll
        for (int qq = 0; qq < 8; ++qq) {
            const int q   = tid + qq * NT;    // 0..1023 quad index
            const int row = q >> 2;           // b*16+o
            const int xp  = (q & 3) * 4;      // 0,4,8,12
            float4 a = s0[q], b4 = s1[q], c4 = s2[q], d4 = s3[q];
            float4 r;
            r.x = ((a.x + b4.x) + c4.x) + d4.x;
            r.y = ((a.y + b4.y) + c4.y) + d4.y;
            r.z = ((a.z + b4.z) + c4.z) + d4.z;
            r.w = ((a.w + b4.w) + c4.w) + d4.w;
            // out float offset = row*3844 + y*62 + x0 + xp : always even
            float* g = out + row * (OH_ * OW_) + y * OW_ + x0 + xp;
            if (xp + 4 <= xt) {
                stg_v2(g,     r.x, r.y);
                stg_v2(g + 2, r.z, r.w);
            } else if (xp < xt) {            // xt==14, xp==12
                stg_v2(g,     r.x, r.y);
            }
        }
    }
}

extern "C" void kernel_launch(void* const* d_in, const int* in_sizes, int n_in,
                              void* d_out, int out_size) {
    const float* x = (const float*)d_in[0];
    const float* w = (const float*)d_in[1];
    float* out = (float*)d_out;

    dim3 grid((OW_ + TX - 1) / TX, OH_, 4);   // (4, 62, 4) = 992 blocks
    lc2d_kernel<<<grid, NT>>>(x, w, out);
}

// round 15
// speedup vs baseline: 1.0028x; 1.0028x over previous
#include <cuda_runtime.h>
#include <cuda_bf16.h>
#include <cstdint>

// LocallyConnected2d: out[b,o,y,x] = sum_{c,k} x[b,c,y+i,x+j] * w[o,c,y,x,k]
// B=16, C_IN=16, C_OUT=16, H=W=64, OH=OW=62, K=3x3.
//
// R15: c-split 2 (z=0 -> out, z=1 -> one scratch buffer; all 496 blocks
// resident at once) + R9 compute core (128 thr, 8b x 4o, LDS.128 x quads,
// 16B cp.async w, triple buffer) + high-MLP sum kernel (out += s0, 2 float4
// per thread, streaming). Fixed-order add -> deterministic. No memset.

#define B_  16
#define CIN 16
#define CO  16
#define H_  64
#define W_  64
#define OH_ 62
#define OW_ 62
#define TX  16
#define NT  128

#define NC  8                       // channels per block (2-way c split)
#define WROW 148                    // weight smem row stride (floats, 16B mult)
#define WBUF (CO * WROW)            // 2368 floats
#define XBUF (4 * 3 * 80)           // 960 floats: [bquad][row][col*4 + bl]
#define BQS  240                    // bquad stride (floats)

#define WOSTRIDE (CIN * OH_ * OW_ * 9)   // weight float stride per o
#define WCSTRIDE (OH_ * OW_ * 9)         // weight float stride per c
#define XCSTRIDE (H_ * W_)               // x float stride per c

#define NOUT (B_ * CO * OH_ * OW_)       // 984064 floats (divisible by 4)
#define N4   (NOUT / 4)                  // 246016 float4s

__device__ __align__(16) float g_scratch[NOUT];

__device__ __forceinline__ void ffma2(unsigned long long& d,
                                      unsigned long long a,
                                      unsigned long long b) {
    asm("fma.rn.f32x2 %0, %1, %2, %0;" : "+l"(d) : "l"(a), "l"(b));
}

__device__ __forceinline__ unsigned long long bcast2(float v) {
    unsigned long long p;
    asm("mov.b64 %0, {%1, %1};" : "=l"(p) : "f"(v));
    return p;
}

__device__ __forceinline__ void cp_async16(uint32_t dst, const float* src) {
    asm volatile("cp.async.cg.shared.global [%0], [%1], 16;\n"
                 :: "r"(dst), "l"(src));
}

__device__ __forceinline__ void cp_async4(uint32_t dst, const float* src, int sz) {
    asm volatile("cp.async.ca.shared.global [%0], [%1], 4, %2;\n"
                 :: "r"(dst), "l"(src), "r"(sz));
}

__device__ __forceinline__ float4 ldcs4(const float4* p) {
    float4 v;
    asm volatile("ld.global.cs.v4.f32 {%0,%1,%2,%3}, [%4];"
                 : "=f"(v.x), "=f"(v.y), "=f"(v.z), "=f"(v.w) : "l"(p));
    return v;
}

__device__ __forceinline__ void stcs4(float4* p, float4 v) {
    asm volatile("st.global.cs.v4.f32 [%0], {%1,%2,%3,%4};"
                 :: "l"(p), "f"(v.x), "f"(v.y), "f"(v.z), "f"(v.w) : "memory");
}

// out += scratch: 2 quads/thread (8 loads in flight), 481 blocks.
__global__ __launch_bounds__(256)
void sum_kernel(float* __restrict__ out) {
    const int base = blockIdx.x * 512 + threadIdx.x;

    float4 a[2], s[2];
    bool ok[2];
    #pragma unroll
    for (int q = 0; q < 2; ++q) {
        const int i = base + q * 256;
        ok[q] = (i < N4);
        const int ii = ok[q] ? i : 0;
        a[q] = ldcs4(reinterpret_cast<const float4*>(out) + ii);
        s[q] = ldcs4(reinterpret_cast<const float4*>(g_scratch) + ii);
    }
    #pragma unroll
    for (int q = 0; q < 2; ++q) {
        if (ok[q]) {
            float4 r;
            r.x = a[q].x + s[q].x;
            r.y = a[q].y + s[q].y;
            r.z = a[q].z + s[q].z;
            r.w = a[q].w + s[q].w;
            stcs4(reinterpret_cast<float4*>(out) + base + q * 256, r);
        }
    }
}

__global__ __launch_bounds__(NT, 5)
void lc2d_kernel(const float* __restrict__ xin,
                 const float* __restrict__ wgt,
                 float* __restrict__ out) {
    __shared__ __align__(16) float sh_w[3 * WBUF];
    __shared__ __align__(16) float sh_x[3 * XBUF];

    const int tid = threadIdx.x;
    const int xl  = tid & 15;
    const int grp = tid >> 4;      // 0..7
    const int bh  = grp & 1;       // b half
    const int ob  = grp >> 1;      // o group

    const int y  = blockIdx.y;
    const int x0 = blockIdx.x * TX;
    const int xt = min(TX, OW_ - x0);       // 16 or 14
    const int zz = blockIdx.z;
    const int c0 = zz * NC;
    const int sh = 2 * (y & 1);             // uniform 16B-alignment shift

    const uint32_t shw_base = (uint32_t)__cvta_generic_to_shared(sh_w);
    const uint32_t shx_base = (uint32_t)__cvta_generic_to_shared(sh_x);

    // ---- weight staging descriptors (16B chunks, 5 slots) ----
    const int rowch  = (xt == TX) ? 37 : 32;
    const int nchunk = CO * rowch;
    const float* wcbase = wgt + (((c0 * OH_ + y) * OW_ + x0) * 9) - sh;

    int      wsoff[5];
    uint32_t wdst[5];
    bool     wok[5];
    #pragma unroll
    for (int n = 0; n < 5; ++n) {
        int m = tid + NT * n;
        wok[n] = (m < nchunk);
        int o   = m / rowch;
        int ci4 = (m - o * rowch) * 4;
        if (o > 15) { o = 15; ci4 = 0; }
        wsoff[n] = o * WOSTRIDE + ci4;
        wdst[n]  = (uint32_t)(o * WROW + ci4) * 4;
    }

    // ---- x staging descriptors (4B, b-quad interleaved, 7 slots) ----
    int      xsrcoff[7], xsz[7];
    uint32_t xdst[7];
    bool     xvalid[7];
    #pragma unroll
    for (int n = 0; n < 7; ++n) {
        int m = tid + NT * n;
        xvalid[n] = (m < B_ * 54);
        int b   = m / 54;
        int rem = m - b * 54;
        int r   = rem / 18;
        int cc  = rem - r * 18;
        if (!xvalid[n]) { b = 0; r = 0; cc = 0; }
        bool ok = xvalid[n] && (x0 + cc < W_);
        xsrcoff[n] = (b * CIN) * XCSTRIDE + r * W_ + cc;
        xsz[n]     = ok ? 4 : 0;
        xdst[n] = (uint32_t)((b >> 2) * BQS + r * 80 + cc * 4 + (b & 3)) * 4;
    }
    const float* xbase = xin + (c0 * H_ + y) * W_ + x0;

    unsigned long long acc[4][2][2];    // [oo][q][pair]: b=(bh*2+q)*4+2*pair
    #pragma unroll
    for (int oo = 0; oo < 4; ++oo)
        #pragma unroll
        for (int q = 0; q < 2; ++q) { acc[oo][q][0] = 0ull; acc[oo][q][1] = 0ull; }

    auto stage = [&](int buf, int ci) {
        uint32_t wb = shw_base + (uint32_t)buf * (WBUF * 4);
        const float* wc = wcbase + ci * WCSTRIDE;
        #pragma unroll
        for (int n = 0; n < 5; ++n)
            if (wok[n]) cp_async16(wb + wdst[n], wc + wsoff[n]);
        uint32_t xb = shx_base + (uint32_t)buf * (XBUF * 4);
        const float* xc = xbase + ci * XCSTRIDE;
        #pragma unroll
        for (int n = 0; n < 7; ++n)
            if (xvalid[n])
                cp_async4(xb + xdst[n], xc + xsrcoff[n], xsz[n]);
        asm volatile("cp.async.commit_group;\n" ::: "memory");
    };

    stage(0, 0);
    stage(1, 1);

    int rd = 0;
    #pragma unroll 1
    for (int ci = 0; ci < NC; ++ci) {
        if (ci < NC - 1) {
            asm volatile("cp.async.wait_group 1;\n" ::: "memory");
        } else {
            asm volatile("cp.async.wait_group 0;\n" ::: "memory");
        }
        __syncthreads();

        if (ci + 2 < NC) {
            int st = rd - 1; if (st < 0) st += 3;
            stage(st, ci + 2);
        }

        const float* swb = sh_w + rd * WBUF + sh;
        const float* sxb = sh_x + rd * XBUF + bh * (2 * BQS);

        #pragma unroll
        for (int k = 0; k < 9; ++k) {
            const int i = k / 3;
            const int j = k - i * 3;
            const float* xp = &sxb[i * 80 + (xl + j) * 4];
            ulonglong2 xq0 = *reinterpret_cast<const ulonglong2*>(xp);
            ulonglong2 xq1 = *reinterpret_cast<const ulonglong2*>(xp + BQS);
            #pragma unroll
            for (int oo = 0; oo < 4; ++oo) {
                float wv = swb[(ob * 4 + oo) * WROW + xl * 9 + k];
                unsigned long long wb2 = bcast2(wv);
                ffma2(acc[oo][0][0], xq0.x, wb2);
                ffma2(acc[oo][0][1], xq0.y, wb2);
                ffma2(acc[oo][1][0], xq1.x, wb2);
                ffma2(acc[oo][1][1], xq1.y, wb2);
            }
        }

        ++rd; if (rd == 3) rd = 0;
    }

    // ---- epilogue: plain STG of partials (no atomics, no memset) ----
    float* dst = (zz == 0) ? out : g_scratch;
    if (xl < xt) {
        #pragma unroll
        for (int oo = 0; oo < 4; ++oo) {
            const int o = ob * 4 + oo;
            #pragma unroll
            for (int q = 0; q < 2; ++q) {
                const int bq = (bh * 2 + q) * 4;
                #pragma unroll
                for (int p = 0; p < 2; ++p) {
                    float lo, hi;
                    asm("mov.b64 {%0, %1}, %2;"
                        : "=f"(lo), "=f"(hi) : "l"(acc[oo][q][p]));
                    const int b = bq + 2 * p;
                    dst[((b * CO + o)       * OH_ + y) * OW_ + x0 + xl] = lo;
                    dst[(((b + 1) * CO + o) * OH_ + y) * OW_ + x0 + xl] = hi;
                }
            }
        }
    }
}

extern "C" void kernel_launch(void* const* d_in, const int* in_sizes, int n_in,
                              void* d_out, int out_size) {
    const float* x = (const float*)d_in[0];
    const float* w = (const float*)d_in[1];
    float* out = (float*)d_out;

    dim3 grid((OW_ + TX - 1) / TX, OH_, 2);   // (4, 62, 2) = 496 blocks
    lc2d_kernel<<<grid, NT>>>(x, w, out);

    // out += scratch (fixed order, deterministic)
    sum_kernel<<<(N4 + 511) / 512, 256>>>(out);
}

// round 16
// speedup vs baseline: 1.0992x; 1.0962x over previous
#include <cuda_runtime.h>
#include <cuda_bf16.h>
#include <cstdint>

// LocallyConnected2d: out[b,o,y,x] = sum_{c,k} x[b,c,y+i,x+j] * w[o,c,y,x,k]
// B=16, C_IN=16, C_OUT=16, H=W=64, OH=OW=62, K=3x3.
//
// R16: c-split 2 where each tile's two blocks form a CLUSTER of 2. Partials
// are exchanged via DSMEM (peer shared memory) after cluster.sync; each rank
// reduces half the tile in fixed z0+z1 order and STGs to out. One kernel,
// no scratch globals, no memset, no atomics. Compute core = R9 (128 thr,
// 8b x 4o per thread, LDS.128 x quads, 16B cp.async w, triple buffer).

#define B_  16
#define CIN 16
#define CO  16
#define H_  64
#define W_  64
#define OH_ 62
#define OW_ 62
#define TX  16
#define NT  128

#define NC  8                       // channels per block (2-way c split)
#define WROW 148                    // weight smem row stride (floats, 16B mult)
#define WBUF (CO * WROW)            // 2368 floats
#define XBUF (4 * 3 * 80)           // 960 floats: [bquad][row][col*4 + bl]
#define BQS  240                    // bquad stride (floats)

#define WOSTRIDE (CIN * OH_ * OW_ * 9)   // weight float stride per o
#define WCSTRIDE (OH_ * OW_ * 9)         // weight float stride per c
#define XCSTRIDE (H_ * W_)               // x float stride per c

__device__ __forceinline__ void ffma2(unsigned long long& d,
                                      unsigned long long a,
                                      unsigned long long b) {
    asm("fma.rn.f32x2 %0, %1, %2, %0;" : "+l"(d) : "l"(a), "l"(b));
}

__device__ __forceinline__ unsigned long long bcast2(float v) {
    unsigned long long p;
    asm("mov.b64 %0, {%1, %1};" : "=l"(p) : "f"(v));
    return p;
}

__device__ __forceinline__ void cp_async16(uint32_t dst, const float* src) {
    asm volatile("cp.async.cg.shared.global [%0], [%1], 16;\n"
                 :: "r"(dst), "l"(src));
}

__device__ __forceinline__ void cp_async4(uint32_t dst, const float* src, int sz) {
    asm volatile("cp.async.ca.shared.global [%0], [%1], 4, %2;\n"
                 :: "r"(dst), "l"(src), "r"(sz));
}

__device__ __forceinline__ void stg_v2(float* p, float a, float b) {
    asm volatile("st.global.v2.f32 [%0], {%1, %2};"
                 :: "l"(p), "f"(a), "f"(b) : "memory");
}

__global__ __launch_bounds__(NT, 5) __cluster_dims__(1, 1, 2)
void lc2d_kernel(const float* __restrict__ xin,
                 const float* __restrict__ wgt,
                 float* __restrict__ out) {
    __shared__ __align__(16) float sh_w[3 * WBUF];
    __shared__ __align__(16) float sh_x[3 * XBUF];

    const int tid = threadIdx.x;
    const int xl  = tid & 15;
    const int grp = tid >> 4;      // 0..7
    const int bh  = grp & 1;       // b half
    const int ob  = grp >> 1;      // o group

    const int y  = blockIdx.y;
    const int x0 = blockIdx.x * TX;
    const int xt = min(TX, OW_ - x0);       // 16 or 14
    const int zz = blockIdx.z;              // == cluster rank
    const int c0 = zz * NC;
    const int sh = 2 * (y & 1);             // uniform 16B-alignment shift

    const uint32_t shw_base = (uint32_t)__cvta_generic_to_shared(sh_w);
    const uint32_t shx_base = (uint32_t)__cvta_generic_to_shared(sh_x);

    // ---- weight staging descriptors (16B chunks, 5 slots) ----
    const int rowch  = (xt == TX) ? 37 : 32;
    const int nchunk = CO * rowch;
    const float* wcbase = wgt + (((c0 * OH_ + y) * OW_ + x0) * 9) - sh;

    int      wsoff[5];
    uint32_t wdst[5];
    bool     wok[5];
    #pragma unroll
    for (int n = 0; n < 5; ++n) {
        int m = tid + NT * n;
        wok[n] = (m < nchunk);
        int o   = m / rowch;
        int ci4 = (m - o * rowch) * 4;
        if (o > 15) { o = 15; ci4 = 0; }
        wsoff[n] = o * WOSTRIDE + ci4;
        wdst[n]  = (uint32_t)(o * WROW + ci4) * 4;
    }

    // ---- x staging descriptors (4B, b-quad interleaved, 7 slots) ----
    int      xsrcoff[7], xsz[7];
    uint32_t xdst[7];
    bool     xvalid[7];
    #pragma unroll
    for (int n = 0; n < 7; ++n) {
        int m = tid + NT * n;
        xvalid[n] = (m < B_ * 54);
        int b   = m / 54;
        int rem = m - b * 54;
        int r   = rem / 18;
        int cc  = rem - r * 18;
        if (!xvalid[n]) { b = 0; r = 0; cc = 0; }
        bool ok = xvalid[n] && (x0 + cc < W_);
        xsrcoff[n] = (b * CIN) * XCSTRIDE + r * W_ + cc;
        xsz[n]     = ok ? 4 : 0;
        xdst[n] = (uint32_t)((b >> 2) * BQS + r * 80 + cc * 4 + (b & 3)) * 4;
    }
    const float* xbase = xin + (c0 * H_ + y) * W_ + x0;

    unsigned long long acc[4][2][2];    // [oo][q][pair]: b=(bh*2+q)*4+2*pair
    #pragma unroll
    for (int oo = 0; oo < 4; ++oo)
        #pragma unroll
        for (int q = 0; q < 2; ++q) { acc[oo][q][0] = 0ull; acc[oo][q][1] = 0ull; }

    auto stage = [&](int buf, int ci) {
        uint32_t wb = shw_base + (uint32_t)buf * (WBUF * 4);
        const float* wc = wcbase + ci * WCSTRIDE;
        #pragma unroll
        for (int n = 0; n < 5; ++n)
            if (wok[n]) cp_async16(wb + wdst[n], wc + wsoff[n]);
        uint32_t xb = shx_base + (uint32_t)buf * (XBUF * 4);
        const float* xc = xbase + ci * XCSTRIDE;
        #pragma unroll
        for (int n = 0; n < 7; ++n)
            if (xvalid[n])
                cp_async4(xb + xdst[n], xc + xsrcoff[n], xsz[n]);
        asm volatile("cp.async.commit_group;\n" ::: "memory");
    };

    stage(0, 0);
    stage(1, 1);

    int rd = 0;
    #pragma unroll 1
    for (int ci = 0; ci < NC; ++ci) {
        if (ci < NC - 1) {
            asm volatile("cp.async.wait_group 1;\n" ::: "memory");
        } else {
            asm volatile("cp.async.wait_group 0;\n" ::: "memory");
        }
        __syncthreads();

        if (ci + 2 < NC) {
            int st = rd - 1; if (st < 0) st += 3;
            stage(st, ci + 2);
        }

        const float* swb = sh_w + rd * WBUF + sh;
        const float* sxb = sh_x + rd * XBUF + bh * (2 * BQS);

        #pragma unroll
        for (int k = 0; k < 9; ++k) {
            const int i = k / 3;
            const int j = k - i * 3;
            const float* xp = &sxb[i * 80 + (xl + j) * 4];
            ulonglong2 xq0 = *reinterpret_cast<const ulonglong2*>(xp);
            ulonglong2 xq1 = *reinterpret_cast<const ulonglong2*>(xp + BQS);
            #pragma unroll
            for (int oo = 0; oo < 4; ++oo) {
                float wv = swb[(ob * 4 + oo) * WROW + xl * 9 + k];
                unsigned long long wb2 = bcast2(wv);
                ffma2(acc[oo][0][0], xq0.x, wb2);
                ffma2(acc[oo][0][1], xq0.y, wb2);
                ffma2(acc[oo][1][0], xq1.x, wb2);
                ffma2(acc[oo][1][1], xq1.y, wb2);
            }
        }

        ++rd; if (rd == 3) rd = 0;
    }

    // ---- park partial in smem (reuse sh_w: 4096 floats, [row=b*16+o][xl]) ----
    __syncthreads();                 // all compute reads of sh_w done
    float* part = sh_w;
    #pragma unroll
    for (int oo = 0; oo < 4; ++oo) {
        const int o = ob * 4 + oo;
        #pragma unroll
        for (int q = 0; q < 2; ++q) {
            const int bq = (bh * 2 + q) * 4;
            #pragma unroll
            for (int p = 0; p < 2; ++p) {
                float lo, hi;
                asm("mov.b64 {%0, %1}, %2;"
                    : "=f"(lo), "=f"(hi) : "l"(acc[oo][q][p]));
                const int b = bq + 2 * p;
                part[((b * CO + o)       << 4) + xl] = lo;
                part[(((b + 1) * CO + o) << 4) + xl] = hi;
            }
        }
    }

    // ---- cluster barrier: peer's partial visible after this ----
    asm volatile("barrier.cluster.arrive.aligned;" ::: "memory");
    asm volatile("barrier.cluster.wait.aligned;"   ::: "memory");

    // ---- each rank reduces its half (rows [zz*128, zz*128+128)) ----
    {
        const uint32_t part_u32 = shw_base;      // part == sh_w
        uint32_t peer_base;
        asm("mapa.shared::cluster.u32 %0, %1, %2;"
            : "=r"(peer_base) : "r"(part_u32), "r"(zz ^ 1));

        #pragma unroll
        for (int t = 0; t < 4; ++t) {
            const int f   = tid + t * NT;        // 0..511 float4 index
            const int row = zz * 128 + (f >> 2); // b*16+o
            const int xp  = (f & 3) * 4;
            const uint32_t off = (uint32_t)(((row & 127) + (zz ? 128 : 0)) * 16 + xp) * 4;
            // local quad
            float4 l = *reinterpret_cast<const float4*>(
                reinterpret_cast<const char*>(part) + off);
            // peer quad via DSMEM
            float4 r;
            asm volatile("ld.shared::cluster.v4.f32 {%0,%1,%2,%3}, [%4];"
                         : "=f"(r.x), "=f"(r.y), "=f"(r.z), "=f"(r.w)
                         : "r"(peer_base + off));
            // fixed order: z0 partial + z1 partial
            float4 s;
            if (zz == 0) {
                s.x = l.x + r.x; s.y = l.y + r.y; s.z = l.z + r.z; s.w = l.w + r.w;
            } else {
                s.x = r.x + l.x; s.y = r.y + l.y; s.z = r.z + l.z; s.w = r.w + l.w;
            }
            float* g = out + row * (OH_ * OW_) + y * OW_ + x0 + xp;
            if (xp + 4 <= xt) {
                stg_v2(g,     s.x, s.y);
                stg_v2(g + 2, s.z, s.w);
            } else if (xp < xt) {            // xt==14, xp==12
                stg_v2(g,     s.x, s.y);
            }
        }
    }

    // ---- don't exit while peer may still read our smem ----
    asm volatile("barrier.cluster.arrive.aligned;" ::: "memory");
    asm volatile("barrier.cluster.wait.aligned;"   ::: "memory");
}

extern "C" void kernel_launch(void* const* d_in, const int* in_sizes, int n_in,
                              void* d_out, int out_size) {
    const float* x = (const float*)d_in[0];
    const float* w = (const float*)d_in[1];
    float* out = (float*)d_out;

    dim3 grid((OW_ + TX - 1) / TX, OH_, 2);   // (4, 62, 2) = 496 blocks
    lc2d_kernel<<<grid, NT>>>(x, w, out);
}